// round 5
// baseline (speedup 1.0000x reference)
#include <cuda_runtime.h>
#include <cuda_bf16.h>

#define B_ 8
#define H_ 12
#define N_ 577
#define HD_ 64
#define BH_ (B_*H_)            // 96
#define NTOK (BH_*N_)          // 55392
#define NNU  332929u           // N*N
#define TOTAL (96u * 332929u)  // 31,961,184 (divisible by 4)
#define TOTAL4 (TOTAL / 4u)    // 7,990,296
#define LOG2E 1.4426950408889634f

typedef unsigned long long u64;

// Per-token quadratic-form coefficients, PRE-SCALED by log2(e):
// p = exp2(c.x*dx^2 + c.y*dx*dy + c.z*dy^2)
__device__ float4 g_coef4[NTOK];

// ---------------- f32x2 packed-math helpers (Blackwell dual-FP32) ----------
#define PK2(o, lo, hi) asm("mov.b64 %0,{%1,%2};" : "=l"(o) : "r"(__float_as_uint(lo)), "r"(__float_as_uint(hi)))
#define UPK2(lo, hi, in) do { unsigned _l,_h; \
    asm("mov.b64 {%0,%1},%2;" : "=r"(_l), "=r"(_h) : "l"(in)); \
    lo = __uint_as_float(_l); hi = __uint_as_float(_h); } while(0)
#define MUL2(o,a,b)   asm("mul.rn.f32x2 %0,%1,%2;"    : "=l"(o) : "l"(a), "l"(b))
#define FMA2(o,a,b,c) asm("fma.rn.f32x2 %0,%1,%2,%3;" : "=l"(o) : "l"(a), "l"(b), "l"(c))
#define ADD2(o,a,b)   asm("add.rn.f32x2 %0,%1,%2;"    : "=l"(o) : "l"(a), "l"(b))

__device__ __forceinline__ float ex2a(float x){ float r; asm("ex2.approx.f32 %0,%1;" : "=f"(r) : "f"(x)); return r; }
__device__ __forceinline__ float rcpa(float x){ float r; asm("rcp.approx.f32 %0,%1;" : "=f"(r) : "f"(x)); return r; }

// ---------------------------------------------------------------------------
// Kernel 1: sigma MLP. FOUR threads per token (16 hidden units each),
// shfl_xor quad-reduction. 256-thread blocks, ~35 regs -> high occupancy.
// ---------------------------------------------------------------------------
__global__ __launch_bounds__(256) void mlp_kernel(
    const float* __restrict__ q,
    const float* __restrict__ W1,
    const float* __restrict__ b1,
    const float* __restrict__ W2,
    const float* __restrict__ b2)
{
    __shared__ float4 w1s[64 * 16];   // [k][j4]
    __shared__ float  b1s[64];
    __shared__ float  w2s[64 * 3];
    __shared__ float  b2s[3];

    const int tid = threadIdx.x;
    for (int idx = tid; idx < 1024; idx += 256) w1s[idx] = ((const float4*)W1)[idx];
    if (tid < 64)  b1s[tid] = b1[tid];
    if (tid < 192) w2s[tid] = W2[tid];
    if (tid < 3)   b2s[tid] = b2[tid];
    __syncthreads();

    int token = blockIdx.x * 64 + (tid >> 2);
    if (token >= NTOK) token = NTOK - 1;        // duplicate write, same value: benign
    const int qt = tid & 3;                      // which 16 hidden units

    const float4* q4 = (const float4*)(q + (size_t)token * HD_);

    float h[16];
    #pragma unroll
    for (int j = 0; j < 16; j++) h[j] = b1s[qt * 16 + j];

    const int jbase = qt * 4;                    // float4 offset into 16-wide row
    #pragma unroll 4
    for (int k4 = 0; k4 < 16; k4++) {
        float4 qv = q4[k4];
        float qk[4] = {qv.x, qv.y, qv.z, qv.w};
        #pragma unroll
        for (int kk = 0; kk < 4; kk++) {
            const float qc = qk[kk];
            const int krow = (k4 * 4 + kk) * 16 + jbase;
            #pragma unroll
            for (int j4 = 0; j4 < 4; j4++) {
                float4 w = w1s[krow + j4];
                h[4*j4+0] = fmaf(qc, w.x, h[4*j4+0]);
                h[4*j4+1] = fmaf(qc, w.y, h[4*j4+1]);
                h[4*j4+2] = fmaf(qc, w.z, h[4*j4+2]);
                h[4*j4+3] = fmaf(qc, w.w, h[4*j4+3]);
            }
        }
    }

    float s0 = 0.f, s1 = 0.f, s2 = 0.f;
    #pragma unroll
    for (int j = 0; j < 16; j++) {
        float x = h[j];
        float g = 0.5f * x * (1.0f + erff(x * 0.70710678118654752f));  // exact gelu
        const int jg = (qt * 16 + j) * 3;
        s0 = fmaf(g, w2s[jg+0], s0);
        s1 = fmaf(g, w2s[jg+1], s1);
        s2 = fmaf(g, w2s[jg+2], s2);
    }
    // quad reduction (lanes of a token differ only in bits 0..1)
    s0 += __shfl_xor_sync(0xffffffffu, s0, 1);
    s1 += __shfl_xor_sync(0xffffffffu, s1, 1);
    s2 += __shfl_xor_sync(0xffffffffu, s2, 1);
    s0 += __shfl_xor_sync(0xffffffffu, s0, 2);
    s1 += __shfl_xor_sync(0xffffffffu, s1, 2);
    s2 += __shfl_xor_sync(0xffffffffu, s2, 2);

    if (qt == 0) {
        s0 += b2s[0]; s1 += b2s[1]; s2 += b2s[2];
        float sx  = fmaxf(s0, 0.0f) + 1.0f;
        float sy  = fmaxf(s1, 0.0f) + 1.0f;
        float rho = 0.99f * tanhf(s2);
        float sxx = sx * sx;
        float syy = sy * sy;
        float sxy = rho * sx * sy;
        float det = sxx * syy - sxy * sxy;       // > 0 always (rho^2 < 0.9801)
        float rdet = 1.0f / det;
        // coefficients pre-scaled by log2(e) so mask kernel uses raw EX2
        g_coef4[token] = make_float4(-0.5f * syy * rdet * LOG2E,
                                              sxy * rdet * LOG2E,
                                     -0.5f * sxx * rdet * LOG2E, 0.f);
    }
}

// ---------------------------------------------------------------------------
// Kernel 2: elementwise mask (row-max provably 1.0 -> no reduction).
// mask = 1/(1+r^10), r = (1-p)(1-u)/(p*u), p = clip(exp2(w'), EPS, 1-EPS).
// Heavy chains run as f32x2 packed pairs; EX2/RCP/clamps scalar.
// ---------------------------------------------------------------------------
__device__ __forceinline__ u64 mask_pair(u64 dx, u64 dy,
                                         u64 a0, u64 a1, u64 a2,
                                         u64 uu, u64 ONE2, u64 NEG12)
{
    u64 xx, xy, yy, w;
    MUL2(xx, dx, dx); MUL2(xy, dx, dy); MUL2(yy, dy, dy);
    MUL2(w, a2, yy); FMA2(w, a1, xy, w); FMA2(w, a0, xx, w);
    float w0, w1; UPK2(w0, w1, w);
    float p0 = ex2a(w0), p1 = ex2a(w1);
    p0 = fminf(fmaxf(p0, 1e-6f), 0.999999f);
    p1 = fminf(fmaxf(p1, 1e-6f), 0.999999f);
    u64 p; PK2(p, p0, p1);
    u64 omp, omu, num, den;
    FMA2(omp, p,  NEG12, ONE2);     // 1-p
    FMA2(omu, uu, NEG12, ONE2);     // 1-u
    MUL2(num, omp, omu);
    MUL2(den, p, uu);
    float d0, d1; UPK2(d0, d1, den);
    u64 rd; PK2(rd, rcpa(d0), rcpa(d1));
    u64 r, r2, r4, r8, r10, s;
    MUL2(r, num, rd);
    MUL2(r2, r, r); MUL2(r4, r2, r2); MUL2(r8, r4, r4); MUL2(r10, r8, r2);
    ADD2(s, r10, ONE2);             // overflow->inf->mask 0; underflow->0->mask 1 (matches ref)
    float s0, s1; UPK2(s0, s1, s);
    u64 res; PK2(res, rcpa(s0), rcpa(s1));
    return res;
}

__device__ __forceinline__ float mask_lane_s(float uu, float dx, float dy, float4 c)
{
    float w = fmaf(c.x, dx*dx, fmaf(c.y, dx*dy, c.z * (dy*dy)));
    float p = ex2a(w);
    p = fminf(fmaxf(p, 1e-6f), 0.999999f);
    float num = (1.0f - p) * (1.0f - uu);
    float r   = num * rcpa(p * uu);
    float r2 = r * r;
    float r4 = r2 * r2;
    float r10 = r4 * r4 * r2;
    return rcpa(1.0f + r10);
}

__global__ __launch_bounds__(256) void mask_kernel(
    const float* __restrict__ u,
    const float* __restrict__ dists,
    float* __restrict__ out)
{
    const unsigned idx4 = blockIdx.x * 256u + threadIdx.x;
    if (idx4 >= TOTAL4) return;
    const unsigned e = idx4 * 4u;

    unsigned bh  = e / NNU;
    unsigned rem = e - bh * NNU;
    unsigned i   = rem / 577u;
    unsigned j   = rem - i * 577u;

    const float4 u4 = __ldcs((const float4*)(u + e));
    const float2* __restrict__ d2 = (const float2*)dists;

    if (j <= 573u) {
        // all 4 lanes in one (bh,i) row
        const float4 c = g_coef4[bh * 577u + i];
        const float2* dp = d2 + (size_t)i * 577u + j;
        float2 d0 = dp[0], d1 = dp[1], dd2 = dp[2], d3 = dp[3];

        u64 ONE2, NEG12;
        PK2(ONE2, 1.0f, 1.0f);
        PK2(NEG12, -1.0f, -1.0f);
        u64 a0, a1, a2;
        PK2(a0, c.x, c.x); PK2(a1, c.y, c.y); PK2(a2, c.z, c.z);

        u64 dxA, dyA, dxB, dyB, uA, uB;
        PK2(dxA, d0.x, d1.x); PK2(dyA, d0.y, d1.y);
        PK2(dxB, dd2.x, d3.x); PK2(dyB, dd2.y, d3.y);
        PK2(uA, u4.x, u4.y); PK2(uB, u4.z, u4.w);

        u64 mA = mask_pair(dxA, dyA, a0, a1, a2, uA, ONE2, NEG12);
        u64 mB = mask_pair(dxB, dyB, a0, a1, a2, uB, ONE2, NEG12);

        float4 res;
        UPK2(res.x, res.y, mA);
        UPK2(res.z, res.w, mB);
        __stcs((float4*)(out + e), res);
    } else {
        // row-crossing vector (~0.7%): per-lane carry, scalar math
        float rl[4];
        const float ul[4] = {u4.x, u4.y, u4.z, u4.w};
        #pragma unroll
        for (int k = 0; k < 4; k++) {
            unsigned jk = j + k, ik = i, bhk = bh;
            if (jk >= 577u) { jk -= 577u; ik += 1u; if (ik >= 577u) { ik = 0u; bhk += 1u; } }
            const float4 c = g_coef4[bhk * 577u + ik];
            const float2 d = d2[(size_t)ik * 577u + jk];
            rl[k] = mask_lane_s(ul[k], d.x, d.y, c);
        }
        __stcs((float4*)(out + e), make_float4(rl[0], rl[1], rl[2], rl[3]));
    }
}

extern "C" void kernel_launch(void* const* d_in, const int* in_sizes, int n_in,
                              void* d_out, int out_size)
{
    const float* query = (const float*)d_in[0];
    const float* W1    = (const float*)d_in[1];
    const float* b1    = (const float*)d_in[2];
    const float* W2    = (const float*)d_in[3];
    const float* b2    = (const float*)d_in[4];
    const float* u     = (const float*)d_in[5];
    const float* dists = (const float*)d_in[6];
    float* out = (float*)d_out;

    mlp_kernel<<<(NTOK + 63) / 64, 256>>>(query, W1, b1, W2, b2);

    const unsigned nb = (TOTAL4 + 255u) / 256u;   // 31213
    mask_kernel<<<nb, 256>>>(u, dists, out);
}

// round 6
// speedup vs baseline: 1.1817x; 1.1817x over previous
#include <cuda_runtime.h>
#include <cuda_bf16.h>

#define B_ 8
#define H_ 12
#define N_ 577
#define HD_ 64
#define BH_ (B_*H_)            // 96
#define NTOK (BH_*N_)          // 55392
#define NNU  332929u           // N*N
#define SLAB (12u*NNU)         // one batch slab: 3,995,148 (divisible by 4)
#define SLAB4 (SLAB/4u)        // 998,787
#define LOG2E 1.4426950408889634f

// Per-token quadratic-form coefficients, PRE-SCALED by log2(e):
// p = exp2(c.x*dx^2 + c.y*dx*dy + c.z*dy^2)
__device__ float4 g_coef4[NTOK];

__device__ __forceinline__ float ex2a(float x){ float r; asm("ex2.approx.f32 %0,%1;" : "=f"(r) : "f"(x)); return r; }
__device__ __forceinline__ float rcpa(float x){ float r; asm("rcp.approx.f32 %0,%1;" : "=f"(r) : "f"(x)); return r; }

// ---------------------------------------------------------------------------
// Kernel 1: sigma MLP. Two threads per token (32 hidden units each),
// shfl_xor pair-reduction. (Best measured config: R4, ~36us.)
// ---------------------------------------------------------------------------
__global__ __launch_bounds__(256) void mlp_kernel(
    const float* __restrict__ q,
    const float* __restrict__ W1,
    const float* __restrict__ b1,
    const float* __restrict__ W2,
    const float* __restrict__ b2)
{
    __shared__ float4 w1s[64 * 16];   // [k][j4]
    __shared__ float  b1s[64];
    __shared__ float  w2s[64 * 3];
    __shared__ float  b2s[3];

    const int tid = threadIdx.x;
    for (int idx = tid; idx < 1024; idx += 256) w1s[idx] = ((const float4*)W1)[idx];
    if (tid < 64)  b1s[tid] = b1[tid];
    if (tid < 192) w2s[tid] = W2[tid];
    if (tid < 3)   b2s[tid] = b2[tid];
    __syncthreads();

    int token = blockIdx.x * 128 + (tid >> 1);
    if (token >= NTOK) token = NTOK - 1;       // duplicate write, same value: benign
    const int half = tid & 1;                   // which 32 hidden units

    const float4* q4 = (const float4*)(q + (size_t)token * HD_);

    float h[32];
    #pragma unroll
    for (int j = 0; j < 32; j++) h[j] = b1s[half * 32 + j];

    const int jbase = half * 8;                 // float4 offset into 16-wide row
    #pragma unroll 4
    for (int k4 = 0; k4 < 16; k4++) {
        float4 qv = q4[k4];
        float qk[4] = {qv.x, qv.y, qv.z, qv.w};
        #pragma unroll
        for (int kk = 0; kk < 4; kk++) {
            const float qc = qk[kk];
            const int krow = (k4 * 4 + kk) * 16 + jbase;
            #pragma unroll
            for (int j4 = 0; j4 < 8; j4++) {
                float4 w = w1s[krow + j4];
                h[4*j4+0] = fmaf(qc, w.x, h[4*j4+0]);
                h[4*j4+1] = fmaf(qc, w.y, h[4*j4+1]);
                h[4*j4+2] = fmaf(qc, w.z, h[4*j4+2]);
                h[4*j4+3] = fmaf(qc, w.w, h[4*j4+3]);
            }
        }
    }

    float s0 = 0.f, s1 = 0.f, s2 = 0.f;
    #pragma unroll 8
    for (int j = 0; j < 32; j++) {
        float x = h[j];
        float g = 0.5f * x * (1.0f + erff(x * 0.70710678118654752f));  // exact gelu
        const int jg = (half * 32 + j) * 3;
        s0 = fmaf(g, w2s[jg+0], s0);
        s1 = fmaf(g, w2s[jg+1], s1);
        s2 = fmaf(g, w2s[jg+2], s2);
    }
    // pair reduction (lanes differ only in bit 0; all lanes active)
    s0 += __shfl_xor_sync(0xffffffffu, s0, 1);
    s1 += __shfl_xor_sync(0xffffffffu, s1, 1);
    s2 += __shfl_xor_sync(0xffffffffu, s2, 1);

    if (half == 0) {
        s0 += b2s[0]; s1 += b2s[1]; s2 += b2s[2];
        float sx  = fmaxf(s0, 0.0f) + 1.0f;
        float sy  = fmaxf(s1, 0.0f) + 1.0f;
        float rho = 0.99f * tanhf(s2);
        float sxx = sx * sx;
        float syy = sy * sy;
        float sxy = rho * sx * sy;
        float det = sxx * syy - sxy * sxy;      // > 0 always (rho^2 < 0.9801)
        float rdet = 1.0f / det;
        // w' = log2e * (-0.5*inv00*dx^2 - inv01*dx*dy - 0.5*inv11*dy^2)
        g_coef4[token] = make_float4(-0.5f * syy * rdet * LOG2E,
                                              sxy * rdet * LOG2E,
                                     -0.5f * sxx * rdet * LOG2E, 0.f);
    }
}

// ---------------------------------------------------------------------------
// Kernel 2: elementwise mask. Row-max provably 1.0 (PD form => w<=0; CLS col
// gives w=0 in every row) -> no reduction.
// mask = 1/(1+r^10), r = (1-p)(1-u)/(p*u), p = clip(exp2(w'), EPS, 1-EPS).
//
// Structure: thread owns a fixed float4 position within ONE batch slab
// (12*NNU elements, divisible by 4) and loops over the 8 batches.
// Slab stride 12*NNU == 0 mod 4, so float4 alignment holds for every b.
// dists loads, squares, and index math are amortized 8x.
// ---------------------------------------------------------------------------
__device__ __forceinline__ float mask_lane(float uu, float xx, float xy, float yy,
                                           float4 c)
{
    float w = fmaf(c.x, xx, fmaf(c.y, xy, c.z * yy));
    float p = ex2a(w);
    p = fminf(fmaxf(p, 1e-6f), 0.999999f);
    float num = (1.0f - p) * (1.0f - uu);
    float r   = num * rcpa(p * uu);
    float r2 = r * r;
    float r4 = r2 * r2;
    float r10 = r4 * r4 * r2;      // inf -> mask 0; 0 -> mask 1 (matches ref saturation)
    return rcpa(1.0f + r10);
}

__global__ __launch_bounds__(256) void mask_kernel(
    const float* __restrict__ u,
    const float* __restrict__ dists,
    float* __restrict__ out)
{
    const unsigned v = blockIdx.x * 256u + threadIdx.x;
    if (v >= SLAB4) return;
    const unsigned e0 = v * 4u;                 // position within slab

    unsigned bhl = e0 / NNU;                    // head-local index 0..11
    unsigned rr  = e0 - bhl * NNU;
    unsigned i   = rr / 577u;
    unsigned j   = rr - i * 577u;

    const float2* __restrict__ d2 = (const float2*)dists;

    if (j <= 573u) {
        // all 4 lanes in one (h,i) row: loop-invariant geometry
        const float2* dp = d2 + (size_t)i * 577u + j;
        const float2 d0 = dp[0], d1 = dp[1], dd2 = dp[2], d3 = dp[3];
        const float xx0 = d0.x*d0.x,  xy0 = d0.x*d0.y,  yy0 = d0.y*d0.y;
        const float xx1 = d1.x*d1.x,  xy1 = d1.x*d1.y,  yy1 = d1.y*d1.y;
        const float xx2 = dd2.x*dd2.x, xy2 = dd2.x*dd2.y, yy2 = dd2.y*dd2.y;
        const float xx3 = d3.x*d3.x,  xy3 = d3.x*d3.y,  yy3 = d3.y*d3.y;

        size_t off = e0;
        unsigned ci = bhl * 577u + i;
        #pragma unroll 2
        for (int b = 0; b < 8; b++) {
            const float4 c  = __ldg(&g_coef4[ci]);
            const float4 u4 = __ldcs((const float4*)(u + off));
            float4 res;
            res.x = mask_lane(u4.x, xx0, xy0, yy0, c);
            res.y = mask_lane(u4.y, xx1, xy1, yy1, c);
            res.z = mask_lane(u4.z, xx2, xy2, yy2, c);
            res.w = mask_lane(u4.w, xx3, xy3, yy3, c);
            __stcs((float4*)(out + off), res);
            off += (size_t)SLAB;
            ci  += 12u * 577u;
        }
    } else {
        // row-crossing vector (~0.7% of threads): per-lane carry,
        // geometry still loop-invariant across b
        unsigned ik[4], cik[4];
        float xxl[4], xyl[4], yyl[4];
        #pragma unroll
        for (int k = 0; k < 4; k++) {
            unsigned jk = j + k, ii = i, hh = bhl;
            if (jk >= 577u) { jk -= 577u; ii += 1u; if (ii >= 577u) { ii = 0u; hh += 1u; } }
            ik[k] = 0; (void)ik;
            cik[k] = hh * 577u + ii;
            const float2 d = d2[(size_t)ii * 577u + jk];
            xxl[k] = d.x*d.x; xyl[k] = d.x*d.y; yyl[k] = d.y*d.y;
        }

        size_t off = e0;
        for (int b = 0; b < 8; b++) {
            const float4 u4 = __ldcs((const float4*)(u + off));
            const float ul[4] = {u4.x, u4.y, u4.z, u4.w};
            float rl[4];
            #pragma unroll
            for (int k = 0; k < 4; k++) {
                const float4 c = __ldg(&g_coef4[(unsigned)(b * 12) * 577u + cik[k]]);
                rl[k] = mask_lane(ul[k], xxl[k], xyl[k], yyl[k], c);
            }
            __stcs((float4*)(out + off), make_float4(rl[0], rl[1], rl[2], rl[3]));
            off += (size_t)SLAB;
        }
    }
}

extern "C" void kernel_launch(void* const* d_in, const int* in_sizes, int n_in,
                              void* d_out, int out_size)
{
    const float* query = (const float*)d_in[0];
    const float* W1    = (const float*)d_in[1];
    const float* b1    = (const float*)d_in[2];
    const float* W2    = (const float*)d_in[3];
    const float* b2    = (const float*)d_in[4];
    const float* u     = (const float*)d_in[5];
    const float* dists = (const float*)d_in[6];
    float* out = (float*)d_out;

    mlp_kernel<<<(NTOK + 127) / 128, 256>>>(query, W1, b1, W2, b2);

    const unsigned nb = (SLAB4 + 255u) / 256u;   // 3902
    mask_kernel<<<nb, 256>>>(u, dists, out);
}

// round 8
// speedup vs baseline: 1.3321x; 1.1273x over previous
#include <cuda_runtime.h>
#include <cuda_bf16.h>

#define B_ 8
#define H_ 12
#define N_ 577
#define HD_ 64
#define BH_ (B_*H_)            // 96
#define NTOK (BH_*N_)          // 55392
#define NNU  332929u           // N*N
#define SLAB (12u*NNU)         // one batch slab: 3,995,148 (divisible by 4)
#define SLAB4 (SLAB/4u)        // 998,787
#define NROWS (12u*577u)       // 6924 rows per slab
#define LOG2E 1.4426950408889634f

#define NB_MAIN ((SLAB4 + 255u)/256u)     // 3902
#define N_CROSS 5193u                      // boundaries 577m, m=1..6923, m%4!=0
#define NB_CROSS ((N_CROSS + 255u)/256u)  // 21

// Per-token coefficients, sign-flipped & pre-scaled by log2(e):
// w'' = c.x*dx^2 + c.y*dx*dy + c.z*dy^2  >= 0,  p = exp2(-w'')
__device__ float4 g_coef4[NTOK];

__device__ __forceinline__ float ex2a(float x){ float r; asm("ex2.approx.f32 %0,%1;" : "=f"(r) : "f"(x)); return r; }
__device__ __forceinline__ float rcpa(float x){ float r; asm("rcp.approx.f32 %0,%1;" : "=f"(r) : "f"(x)); return r; }

// ---------------------------------------------------------------------------
// Kernel 1: sigma MLP. Two threads per token (32 hidden units each),
// shfl_xor pair-reduction. (Best measured config — unchanged.)
// ---------------------------------------------------------------------------
__global__ __launch_bounds__(256) void mlp_kernel(
    const float* __restrict__ q,
    const float* __restrict__ W1,
    const float* __restrict__ b1,
    const float* __restrict__ W2,
    const float* __restrict__ b2)
{
    __shared__ float4 w1s[64 * 16];   // [k][j4]
    __shared__ float  b1s[64];
    __shared__ float  w2s[64 * 3];
    __shared__ float  b2s[3];

    const int tid = threadIdx.x;
    for (int idx = tid; idx < 1024; idx += 256) w1s[idx] = ((const float4*)W1)[idx];
    if (tid < 64)  b1s[tid] = b1[tid];
    if (tid < 192) w2s[tid] = W2[tid];
    if (tid < 3)   b2s[tid] = b2[tid];
    __syncthreads();

    int token = blockIdx.x * 128 + (tid >> 1);
    if (token >= NTOK) token = NTOK - 1;       // duplicate write, same value: benign
    const int half = tid & 1;                   // which 32 hidden units

    const float4* q4 = (const float4*)(q + (size_t)token * HD_);

    float h[32];
    #pragma unroll
    for (int j = 0; j < 32; j++) h[j] = b1s[half * 32 + j];

    const int jbase = half * 8;                 // float4 offset into 16-wide row
    #pragma unroll 4
    for (int k4 = 0; k4 < 16; k4++) {
        float4 qv = q4[k4];
        float qk[4] = {qv.x, qv.y, qv.z, qv.w};
        #pragma unroll
        for (int kk = 0; kk < 4; kk++) {
            const float qc = qk[kk];
            const int krow = (k4 * 4 + kk) * 16 + jbase;
            #pragma unroll
            for (int j4 = 0; j4 < 8; j4++) {
                float4 w = w1s[krow + j4];
                h[4*j4+0] = fmaf(qc, w.x, h[4*j4+0]);
                h[4*j4+1] = fmaf(qc, w.y, h[4*j4+1]);
                h[4*j4+2] = fmaf(qc, w.z, h[4*j4+2]);
                h[4*j4+3] = fmaf(qc, w.w, h[4*j4+3]);
            }
        }
    }

    float s0 = 0.f, s1 = 0.f, s2 = 0.f;
    #pragma unroll 8
    for (int j = 0; j < 32; j++) {
        float x = h[j];
        float g = 0.5f * x * (1.0f + erff(x * 0.70710678118654752f));  // exact gelu
        const int jg = (half * 32 + j) * 3;
        s0 = fmaf(g, w2s[jg+0], s0);
        s1 = fmaf(g, w2s[jg+1], s1);
        s2 = fmaf(g, w2s[jg+2], s2);
    }
    s0 += __shfl_xor_sync(0xffffffffu, s0, 1);
    s1 += __shfl_xor_sync(0xffffffffu, s1, 1);
    s2 += __shfl_xor_sync(0xffffffffu, s2, 1);

    if (half == 0) {
        s0 += b2s[0]; s1 += b2s[1]; s2 += b2s[2];
        float sx  = fmaxf(s0, 0.0f) + 1.0f;
        float sy  = fmaxf(s1, 0.0f) + 1.0f;
        float rho = 0.99f * tanhf(s2);
        float sxx = sx * sx;
        float syy = sy * sy;
        float sxy = rho * sx * sy;
        float det = sxx * syy - sxy * sxy;      // > 0 always (rho^2 < 0.9801)
        float rdet = 1.0f / det;
        // POSITIVE quadratic form: w'' = -w * log2e
        g_coef4[token] = make_float4( 0.5f * syy * rdet * LOG2E,
                                     -sxy * rdet * LOG2E,
                                      0.5f * sxx * rdet * LOG2E, 0.f);
    }
}

// ---------------------------------------------------------------------------
// Kernel 2: elementwise mask. Row-max provably 1.0 -> no reduction.
// Odds form: A = (1-p)/p = exp2(w'')-1 (Sterbenz-exact), clamped to the f32
// image of the reference's clip(p, 1e-6, 1-1e-6):
//   A_MIN = (1-f32(1-1e-6))/f32(1-1e-6) = 1.01328e-6
//   A_MAX = (1-f32(1e-6))/f32(1e-6)     = 999999.0
// r = A*(1-u)*rcp(u);  mask = rcp(1 + r^10).
// r^10 overflow->inf->mask 0, underflow->0->mask 1 (matches ref saturation).
//
// Structure: main blocks handle only NON-crossing float4 vectors (branch-free
// warps); the 5193 row-crossing vectors (boundaries at 577m, m%4!=0) are
// handled by NB_CROSS dedicated tail blocks -> no warp issues both paths.
// Each thread loops over the 8 batches (slab stride divisible by 4).
// ---------------------------------------------------------------------------
__device__ __forceinline__ float mask_lane(float uu, float xx, float xy, float yy,
                                           float4 c)
{
    float w = fmaf(c.x, xx, fmaf(c.y, xy, c.z * yy));   // >= 0
    float A = ex2a(w) - 1.0f;
    A = fminf(fmaxf(A, 1.0132800e-06f), 999999.0f);
    float r = A * (1.0f - uu) * rcpa(uu);
    float r2 = r * r;
    float r4 = r2 * r2;
    float r10 = r4 * r4 * r2;
    return rcpa(1.0f + r10);
}

__global__ __launch_bounds__(256, 6) void mask_kernel(
    const float* __restrict__ u,
    const float* __restrict__ dists,
    float* __restrict__ out)
{
    const float2* __restrict__ d2 = (const float2*)dists;
    const unsigned bx = blockIdx.x;

    if (bx < NB_MAIN) {
        const unsigned v = bx * 256u + threadIdx.x;
        if (v >= SLAB4) return;
        const unsigned e0 = v * 4u;

        const unsigned rowg = e0 / 577u;          // 0..6923 (= bhl*577 + i)
        const unsigned j    = e0 - rowg * 577u;
        if (j > 573u) return;                     // crossing vector: tail blocks
        const unsigned i    = rowg % 577u;

        const float2* dp = d2 + (size_t)i * 577u + j;
        const float2 d0 = dp[0], d1 = dp[1], dd2 = dp[2], d3 = dp[3];
        const float xx0 = d0.x*d0.x,   xy0 = d0.x*d0.y,   yy0 = d0.y*d0.y;
        const float xx1 = d1.x*d1.x,   xy1 = d1.x*d1.y,   yy1 = d1.y*d1.y;
        const float xx2 = dd2.x*dd2.x, xy2 = dd2.x*dd2.y, yy2 = dd2.y*dd2.y;
        const float xx3 = d3.x*d3.x,   xy3 = d3.x*d3.y,   yy3 = d3.y*d3.y;

        size_t off = e0;
        unsigned ci = rowg;
        #pragma unroll 2
        for (int b = 0; b < 8; b++) {
            const float4 c  = __ldg(&g_coef4[ci]);
            const float4 u4 = __ldcs((const float4*)(u + off));
            float4 res;
            res.x = mask_lane(u4.x, xx0, xy0, yy0, c);
            res.y = mask_lane(u4.y, xx1, xy1, yy1, c);
            res.z = mask_lane(u4.z, xx2, xy2, yy2, c);
            res.w = mask_lane(u4.w, xx3, xy3, yy3, c);
            __stcs((float4*)(out + off), res);
            off += (size_t)SLAB;
            ci  += NROWS;
        }
    } else {
        // ---- crossing vectors: t -> m (skip m%4==0) -> vector floor(577m/4)
        const unsigned t = (bx - NB_MAIN) * 256u + threadIdx.x;
        if (t >= N_CROSS) return;
        const unsigned m   = t + t / 3u + 1u;     // 1,2,3,5,6,7,9,...
        const unsigned bnd = m * 577u;            // boundary element index
        const unsigned e0  = bnd & ~3u;

        unsigned rowk[4];
        float xxl[4], xyl[4], yyl[4];
        #pragma unroll
        for (int k = 0; k < 4; k++) {
            const unsigned ek = e0 + (unsigned)k;
            const unsigned rg = (ek < bnd) ? (m - 1u) : m;
            rowk[k] = rg;
            const unsigned jk = ek - rg * 577u;
            const unsigned ik = rg % 577u;
            const float2 d = d2[(size_t)ik * 577u + jk];
            xxl[k] = d.x*d.x; xyl[k] = d.x*d.y; yyl[k] = d.y*d.y;
        }

        size_t off = e0;
        for (int b = 0; b < 8; b++) {
            const float4 u4 = __ldcs((const float4*)(u + off));
            const float ul[4] = {u4.x, u4.y, u4.z, u4.w};
            float rl[4];
            const unsigned cb = (unsigned)b * NROWS;
            #pragma unroll
            for (int k = 0; k < 4; k++) {
                const float4 c = __ldg(&g_coef4[cb + rowk[k]]);
                rl[k] = mask_lane(ul[k], xxl[k], xyl[k], yyl[k], c);
            }
            __stcs((float4*)(out + off), make_float4(rl[0], rl[1], rl[2], rl[3]));
            off += (size_t)SLAB;
        }
    }
}

extern "C" void kernel_launch(void* const* d_in, const int* in_sizes, int n_in,
                              void* d_out, int out_size)
{
    const float* query = (const float*)d_in[0];
    const float* W1    = (const float*)d_in[1];
    const float* b1    = (const float*)d_in[2];
    const float* W2    = (const float*)d_in[3];
    const float* b2    = (const float*)d_in[4];
    const float* u     = (const float*)d_in[5];
    const float* dists = (const float*)d_in[6];
    float* out = (float*)d_out;

    mlp_kernel<<<(NTOK + 127) / 128, 256>>>(query, W1, b1, W2, b2);

    mask_kernel<<<NB_MAIN + NB_CROSS, 256>>>(u, dists, out);
}